// round 2
// baseline (speedup 1.0000x reference)
#include <cuda_runtime.h>

// Problem constants
#define BATCH   4096
#define SEQT    512
#define HID     50
#define NBC     32              // batch per CTA
#define NBT     4               // batch per thread
#define BGRP    (NBC / NBT)     // 8 batch-groups
#define NTHREADS (HID * BGRP)   // 400
#define NCTAS   (BATCH / NBC)   // 128
#define HS      51              // padded h stride (float2 units) to break STS bank conflicts

typedef unsigned long long u64;

// ---- f32x2 packed math helpers (sm_100+ PTX) ----
__device__ __forceinline__ void fma2(u64 &acc, u64 a, u64 b) {
    asm("fma.rn.f32x2 %0, %1, %2, %0;" : "+l"(acc) : "l"(a), "l"(b));
}
__device__ __forceinline__ u64 pk2(float a, float b) {
    u64 r;
    unsigned ia = __float_as_uint(a), ib = __float_as_uint(b);
    asm("mov.b64 %0, {%1, %2};" : "=l"(r) : "r"(ia), "r"(ib));
    return r;
}
__device__ __forceinline__ float lo2(u64 v) { return __uint_as_float((unsigned)v); }
__device__ __forceinline__ float hi2(u64 v) { return __uint_as_float((unsigned)(v >> 32)); }

__device__ __forceinline__ float sigmoidf_(float z) {
    return __fdividef(1.0f, 1.0f + __expf(-z));
}
__device__ __forceinline__ float tanhf_(float z) {
    z = fminf(fmaxf(z, -15.0f), 15.0f);   // avoid inf/inf
    float e = __expf(2.0f * z);
    return __fdividef(e - 1.0f, e + 1.0f);
}

// SMEM layout (float2 units):
//  w0if[2500] w0go[2500] w1iif[2500] w1igo[2500] w1hif[2500] w1hgo[2500]
//  bias[300]  (b0if, b0go, b1if, b1go, wxif, wxgo : 50 each)
//  h0[2*NBC*HS = 3264] (double buffered)  h1[3264]
//  fcw[50]+fcb (floats)
#define W_F2    2500
#define BIAS_F2 300
#define HBUF_F2 (NBC * HS)         // 1632 per buffer
#define H_F2    (2 * HBUF_F2)      // 3264 per layer
#define SMEM_F2 (6 * W_F2 + BIAS_F2 + 2 * H_F2)
#define SMEM_BYTES (SMEM_F2 * 8 + 64 * 4)

__global__ __launch_bounds__(NTHREADS, 1)
void lstm_fused_kernel(const float* __restrict__ x,
                       const float* __restrict__ Wih0, const float* __restrict__ Whh0,
                       const float* __restrict__ bih0, const float* __restrict__ bhh0,
                       const float* __restrict__ Wih1, const float* __restrict__ Whh1,
                       const float* __restrict__ bih1, const float* __restrict__ bhh1,
                       const float* __restrict__ fcw_g, const float* __restrict__ fcb_g,
                       float* __restrict__ out)
{
    extern __shared__ float2 sm[];
    float2* w0if  = sm;
    float2* w0go  = w0if  + W_F2;
    float2* w1iif = w0go  + W_F2;
    float2* w1igo = w1iif + W_F2;
    float2* w1hif = w1igo + W_F2;
    float2* w1hgo = w1hif + W_F2;
    float2* biasm = w1hgo + W_F2;     // [0:50) b0if [50:100) b0go [100:150) b1if [150:200) b1go [200:250) wxif [250:300) wxgo
    float2* h0b   = biasm + BIAS_F2;  // 2 buffers of NBC*HS
    float2* h1b   = h0b   + H_F2;
    float*  fcw   = (float*)(h1b + H_F2);  // [0:50) weights, [50] bias

    const int tid = threadIdx.x;

    // ---- stage weights (transposed, gate-paired) into SMEM ----
    for (int idx = tid; idx < W_F2; idx += NTHREADS) {
        int j = idx / HID, u = idx % HID;   // idx = j*50 + u
        w0if [idx] = make_float2(Whh0[(u)         * HID + j], Whh0[(HID   + u) * HID + j]);
        w0go [idx] = make_float2(Whh0[(2*HID + u) * HID + j], Whh0[(3*HID + u) * HID + j]);
        w1iif[idx] = make_float2(Wih1[(u)         * HID + j], Wih1[(HID   + u) * HID + j]);
        w1igo[idx] = make_float2(Wih1[(2*HID + u) * HID + j], Wih1[(3*HID + u) * HID + j]);
        w1hif[idx] = make_float2(Whh1[(u)         * HID + j], Whh1[(HID   + u) * HID + j]);
        w1hgo[idx] = make_float2(Whh1[(2*HID + u) * HID + j], Whh1[(3*HID + u) * HID + j]);
    }
    if (tid < HID) {
        biasm[tid]       = make_float2(bih0[tid] + bhh0[tid],
                                       bih0[HID + tid] + bhh0[HID + tid]);
        biasm[HID + tid] = make_float2(bih0[2*HID + tid] + bhh0[2*HID + tid],
                                       bih0[3*HID + tid] + bhh0[3*HID + tid]);
        biasm[100 + tid] = make_float2(bih1[tid] + bhh1[tid],
                                       bih1[HID + tid] + bhh1[HID + tid]);
        biasm[150 + tid] = make_float2(bih1[2*HID + tid] + bhh1[2*HID + tid],
                                       bih1[3*HID + tid] + bhh1[3*HID + tid]);
        biasm[200 + tid] = make_float2(Wih0[tid],        Wih0[HID + tid]);       // IN=1
        biasm[250 + tid] = make_float2(Wih0[2*HID + tid], Wih0[3*HID + tid]);
        fcw[tid] = fcw_g[tid];
    }
    if (tid == 0) fcw[HID] = fcb_g[0];
    // zero both h double-buffers (h0b..h1b contiguous)
    for (int idx = tid; idx < 2 * H_F2; idx += NTHREADS)
        h0b[idx] = make_float2(0.0f, 0.0f);
    __syncthreads();

    // ---- per-thread setup ----
    const int bg = tid & 7;          // batch group (fast within warp -> weight-broadcast)
    const int u  = tid >> 3;         // hidden unit 0..49
    const int bb = bg * NBT;         // local batch base

    const u64* w0if64  = (const u64*)w0if;
    const u64* w0go64  = (const u64*)w0go;
    const u64* w1iif64 = (const u64*)w1iif;
    const u64* w1igo64 = (const u64*)w1igo;
    const u64* w1hif64 = (const u64*)w1hif;
    const u64* w1hgo64 = (const u64*)w1hgo;

    const u64 rb0if = ((const u64*)biasm)[u];
    const u64 rb0go = ((const u64*)biasm)[HID + u];
    const u64 rb1if = ((const u64*)biasm)[100 + u];
    const u64 rb1go = ((const u64*)biasm)[150 + u];
    const u64 rwxif = ((const u64*)biasm)[200 + u];
    const u64 rwxgo = ((const u64*)biasm)[250 + u];

    float c0[NBT] = {0.f, 0.f, 0.f, 0.f};
    float c1[NBT] = {0.f, 0.f, 0.f, 0.f};

    const float* xp = x + (size_t)(blockIdx.x * NBC + bb) * SEQT;

    int p = 0;
    for (int t = 0; t < SEQT; t++) {
        const int q = p ^ 1;
        // ===== layer 0 =====
        u64 aif[NBT], ago[NBT];
        #pragma unroll
        for (int nb = 0; nb < NBT; nb++) {
            float xv = xp[nb * SEQT + t];
            u64 xx = pk2(xv, xv);
            aif[nb] = rb0if;  fma2(aif[nb], rwxif, xx);
            ago[nb] = rb0go;  fma2(ago[nb], rwxgo, xx);
        }
        {
            const u64* h0p = (const u64*)(h0b + p * HBUF_F2) + bb * HS;
            #pragma unroll 10
            for (int j = 0; j < HID; j++) {
                u64 wif = w0if64[j * HID + u];
                u64 wgo = w0go64[j * HID + u];
                #pragma unroll
                for (int nb = 0; nb < NBT; nb++) {
                    u64 hh = h0p[nb * HS + j];
                    fma2(aif[nb], wif, hh);
                    fma2(ago[nb], wgo, hh);
                }
            }
        }
        float h0new[NBT];
        #pragma unroll
        for (int nb = 0; nb < NBT; nb++) {
            float ig = sigmoidf_(lo2(aif[nb]));
            float fg = sigmoidf_(hi2(aif[nb]));
            float gg = tanhf_(lo2(ago[nb]));
            float og = sigmoidf_(hi2(ago[nb]));
            c0[nb] = fg * c0[nb] + ig * gg;
            h0new[nb] = og * tanhf_(c0[nb]);
        }
        {
            float2* h0w = h0b + q * HBUF_F2 + bb * HS;
            #pragma unroll
            for (int nb = 0; nb < NBT; nb++)
                h0w[nb * HS + u] = make_float2(h0new[nb], h0new[nb]);
        }
        __syncthreads();   // new h0 visible before layer-1 consumes it

        // ===== layer 1 =====
        #pragma unroll
        for (int nb = 0; nb < NBT; nb++) { aif[nb] = rb1if; ago[nb] = rb1go; }
        {
            const u64* h0q = (const u64*)(h0b + q * HBUF_F2) + bb * HS;
            const u64* h1p = (const u64*)(h1b + p * HBUF_F2) + bb * HS;
            #pragma unroll 5
            for (int j = 0; j < HID; j++) {
                u64 wiif = w1iif64[j * HID + u];
                u64 wigo = w1igo64[j * HID + u];
                u64 whif = w1hif64[j * HID + u];
                u64 whgo = w1hgo64[j * HID + u];
                #pragma unroll
                for (int nb = 0; nb < NBT; nb++) {
                    u64 ha = h0q[nb * HS + j];
                    u64 hb = h1p[nb * HS + j];
                    fma2(aif[nb], wiif, ha);
                    fma2(ago[nb], wigo, ha);
                    fma2(aif[nb], whif, hb);
                    fma2(ago[nb], whgo, hb);
                }
            }
        }
        {
            float2* h1w = h1b + q * HBUF_F2 + bb * HS;
            #pragma unroll
            for (int nb = 0; nb < NBT; nb++) {
                float ig = sigmoidf_(lo2(aif[nb]));
                float fg = sigmoidf_(hi2(aif[nb]));
                float gg = tanhf_(lo2(ago[nb]));
                float og = sigmoidf_(hi2(ago[nb]));
                c1[nb] = fg * c1[nb] + ig * gg;
                float h1new = og * tanhf_(c1[nb]);
                h1w[nb * HS + u] = make_float2(h1new, h1new);
            }
        }
        __syncthreads();   // new h1 visible before next step reads it
        p = q;
    }

    // ===== final projection: out[b] = h1_last[b,:] . fcw + fcb =====
    // After T=512 (even) steps, final h1 lives in buffer p == 0.
    if (tid < NBC) {
        const float2* hfin = h1b + 0 * HBUF_F2 + tid * HS;
        float acc = 0.0f;
        #pragma unroll 10
        for (int uu = 0; uu < HID; uu++)
            acc += hfin[uu].x * fcw[uu];
        out[blockIdx.x * NBC + tid] = acc + fcw[HID];
    }
}

extern "C" void kernel_launch(void* const* d_in, const int* in_sizes, int n_in,
                              void* d_out, int out_size)
{
    const float* x    = (const float*)d_in[0];
    const float* Wih0 = (const float*)d_in[1];
    const float* Whh0 = (const float*)d_in[2];
    const float* bih0 = (const float*)d_in[3];
    const float* bhh0 = (const float*)d_in[4];
    const float* Wih1 = (const float*)d_in[5];
    const float* Whh1 = (const float*)d_in[6];
    const float* bih1 = (const float*)d_in[7];
    const float* bhh1 = (const float*)d_in[8];
    const float* fcw  = (const float*)d_in[9];
    const float* fcb  = (const float*)d_in[10];
    float* out = (float*)d_out;

    cudaFuncSetAttribute(lstm_fused_kernel,
                         cudaFuncAttributeMaxDynamicSharedMemorySize, SMEM_BYTES);
    lstm_fused_kernel<<<NCTAS, NTHREADS, SMEM_BYTES>>>(
        x, Wih0, Whh0, bih0, bhh0, Wih1, Whh1, bih1, bhh1, fcw, fcb, out);
}

// round 3
// speedup vs baseline: 2.1625x; 2.1625x over previous
#include <cuda_runtime.h>

// Problem constants
#define BATCH   4096
#define SEQT    512
#define HID     50
#define NBC     32               // batch per CTA
#define NBT     4                // batch per thread
#define BGRP    (NBC / NBT)      // 8
#define NTHREADS (HID * BGRP)    // 400
#define NCTAS   (BATCH / NBC)    // 128
#define JP      52               // padded j extent (h rows 50,51 zeroed; weight cols 50,51 zeroed)
#define HBS     (JP * NBC)       // floats per h buffer = 1664
#define WMAT    (4 * HID * JP)   // floats per weight matrix in smem = 10400

typedef unsigned long long u64;

__device__ __forceinline__ void fma2(u64 &acc, u64 a, u64 b) {
    asm("fma.rn.f32x2 %0, %1, %2, %0;" : "+l"(acc) : "l"(a), "l"(b));
}
__device__ __forceinline__ u64 pk2(float a, float b) {
    u64 r;
    unsigned ia = __float_as_uint(a), ib = __float_as_uint(b);
    asm("mov.b64 %0, {%1, %2};" : "=l"(r) : "r"(ia), "r"(ib));
    return r;
}
__device__ __forceinline__ float lo2(u64 v) { return __uint_as_float((unsigned)v); }
__device__ __forceinline__ float hi2(u64 v) { return __uint_as_float((unsigned)(v >> 32)); }

__device__ __forceinline__ float sigmoidf_(float z) {
    return __fdividef(1.0f, 1.0f + __expf(-z));
}
__device__ __forceinline__ float tanhf_(float z) {
    z = fminf(fmaxf(z, -15.0f), 15.0f);
    float e = __expf(2.0f * z);
    return __fdividef(e - 1.0f, e + 1.0f);
}

// SMEM (floats): w0[WMAT] w1i[WMAT] w1h[WMAT] h0[2*HBS] h1[2*HBS] fcw[52]
#define SMEM_FLOATS (3 * WMAT + 4 * HBS + 52)
#define SMEM_BYTES  (SMEM_FLOATS * 4)

__global__ __launch_bounds__(NTHREADS, 1)
void lstm_fused_kernel(const float* __restrict__ x,
                       const float* __restrict__ Wih0, const float* __restrict__ Whh0,
                       const float* __restrict__ bih0, const float* __restrict__ bhh0,
                       const float* __restrict__ Wih1, const float* __restrict__ Whh1,
                       const float* __restrict__ bih1, const float* __restrict__ bhh1,
                       const float* __restrict__ fcw_g, const float* __restrict__ fcb_g,
                       float* __restrict__ out)
{
    extern __shared__ float smf[];
    float* w0s  = smf;                 // [4*HID][JP]   row = g*HID+u
    float* w1is = w0s  + WMAT;
    float* w1hs = w1is + WMAT;
    float* h0s  = w1hs + WMAT;         // [2][JP][NBC]
    float* h1s  = h0s  + 2 * HBS;
    float* fcws = h1s  + 2 * HBS;      // [0:50) weights, [50] bias

    const int tid = threadIdx.x;

    // ---- stage weights (row-padded to JP, tail cols zeroed) ----
    for (int idx = tid; idx < WMAT; idx += NTHREADS) {
        int row = idx / JP, col = idx - row * JP;
        float a = 0.f, b = 0.f, c = 0.f;
        if (col < HID) {
            a = Whh0[row * HID + col];
            b = Wih1[row * HID + col];
            c = Whh1[row * HID + col];
        }
        w0s[idx]  = a;
        w1is[idx] = b;
        w1hs[idx] = c;
    }
    // zero h buffers (both layers, both double-buffers, incl. pad rows)
    for (int idx = tid; idx < 4 * HBS; idx += NTHREADS)
        h0s[idx] = 0.0f;
    if (tid < HID) fcws[tid] = fcw_g[tid];
    if (tid == 0)  fcws[HID] = fcb_g[0];

    // ---- per-thread setup ----
    const int bg = tid & 7;       // batch group (fast in warp)
    const int u  = tid >> 3;      // hidden unit 0..49
    const int bb = bg * NBT;

    u64 rb0[4], rb1[4], rwx[4];
    #pragma unroll
    for (int g = 0; g < 4; g++) {
        float b0v = bih0[g * HID + u] + bhh0[g * HID + u];
        float b1v = bih1[g * HID + u] + bhh1[g * HID + u];
        float wxv = Wih0[g * HID + u];      // IN = 1
        rb0[g] = pk2(b0v, b0v);
        rb1[g] = pk2(b1v, b1v);
        rwx[g] = pk2(wxv, wxv);
    }
    const float* w0r[4];
    const float* w1ir[4];
    const float* w1hr[4];
    #pragma unroll
    for (int g = 0; g < 4; g++) {
        w0r[g]  = w0s  + (g * HID + u) * JP;
        w1ir[g] = w1is + (g * HID + u) * JP;
        w1hr[g] = w1hs + (g * HID + u) * JP;
    }

    float c0[NBT] = {0.f, 0.f, 0.f, 0.f};
    float c1[NBT] = {0.f, 0.f, 0.f, 0.f};

    const float* xp = x + (size_t)(blockIdx.x * NBC + bb) * SEQT;
    float xv[NBT], xvn[NBT];
    #pragma unroll
    for (int nb = 0; nb < NBT; nb++) xv[nb] = xp[nb * SEQT + 0];

    __syncthreads();

    int p = 0;
    for (int t = 0; t < SEQT; t++) {
        const int q = p ^ 1;
        // prefetch next-step x (hide LDG latency behind the matmuls)
        const int tn = (t + 1 < SEQT) ? t + 1 : t;
        #pragma unroll
        for (int nb = 0; nb < NBT; nb++) xvn[nb] = xp[nb * SEQT + tn];

        // ===== layer 0 : gates = b0 + wx*x + Whh0 @ h0(t-1) =====
        u64 accA[4], accB[4];
        {
            u64 xxA = pk2(xv[0], xv[1]);
            u64 xxB = pk2(xv[2], xv[3]);
            #pragma unroll
            for (int g = 0; g < 4; g++) {
                accA[g] = rb0[g]; fma2(accA[g], rwx[g], xxA);
                accB[g] = rb0[g]; fma2(accB[g], rwx[g], xxB);
            }
        }
        {
            const float* h0p_ = h0s + p * HBS + bb;
            for (int j4 = 0; j4 < JP; j4 += 4) {
                float4 wi = *(const float4*)(w0r[0] + j4);
                float4 wf = *(const float4*)(w0r[1] + j4);
                float4 wg = *(const float4*)(w0r[2] + j4);
                float4 wo = *(const float4*)(w0r[3] + j4);
                ulonglong2 h0v = *(const ulonglong2*)(h0p_ + (j4 + 0) * NBC);
                ulonglong2 h1v = *(const ulonglong2*)(h0p_ + (j4 + 1) * NBC);
                ulonglong2 h2v = *(const ulonglong2*)(h0p_ + (j4 + 2) * NBC);
                ulonglong2 h3v = *(const ulonglong2*)(h0p_ + (j4 + 3) * NBC);
                fma2(accA[0], pk2(wi.x, wi.x), h0v.x); fma2(accB[0], pk2(wi.x, wi.x), h0v.y);
                fma2(accA[1], pk2(wf.x, wf.x), h0v.x); fma2(accB[1], pk2(wf.x, wf.x), h0v.y);
                fma2(accA[2], pk2(wg.x, wg.x), h0v.x); fma2(accB[2], pk2(wg.x, wg.x), h0v.y);
                fma2(accA[3], pk2(wo.x, wo.x), h0v.x); fma2(accB[3], pk2(wo.x, wo.x), h0v.y);
                fma2(accA[0], pk2(wi.y, wi.y), h1v.x); fma2(accB[0], pk2(wi.y, wi.y), h1v.y);
                fma2(accA[1], pk2(wf.y, wf.y), h1v.x); fma2(accB[1], pk2(wf.y, wf.y), h1v.y);
                fma2(accA[2], pk2(wg.y, wg.y), h1v.x); fma2(accB[2], pk2(wg.y, wg.y), h1v.y);
                fma2(accA[3], pk2(wo.y, wo.y), h1v.x); fma2(accB[3], pk2(wo.y, wo.y), h1v.y);
                fma2(accA[0], pk2(wi.z, wi.z), h2v.x); fma2(accB[0], pk2(wi.z, wi.z), h2v.y);
                fma2(accA[1], pk2(wf.z, wf.z), h2v.x); fma2(accB[1], pk2(wf.z, wf.z), h2v.y);
                fma2(accA[2], pk2(wg.z, wg.z), h2v.x); fma2(accB[2], pk2(wg.z, wg.z), h2v.y);
                fma2(accA[3], pk2(wo.z, wo.z), h2v.x); fma2(accB[3], pk2(wo.z, wo.z), h2v.y);
                fma2(accA[0], pk2(wi.w, wi.w), h3v.x); fma2(accB[0], pk2(wi.w, wi.w), h3v.y);
                fma2(accA[1], pk2(wf.w, wf.w), h3v.x); fma2(accB[1], pk2(wf.w, wf.w), h3v.y);
                fma2(accA[2], pk2(wg.w, wg.w), h3v.x); fma2(accB[2], pk2(wg.w, wg.w), h3v.y);
                fma2(accA[3], pk2(wo.w, wo.w), h3v.x); fma2(accB[3], pk2(wo.w, wo.w), h3v.y);
            }
        }
        {
            float gi[4] = {lo2(accA[0]), hi2(accA[0]), lo2(accB[0]), hi2(accB[0])};
            float gf[4] = {lo2(accA[1]), hi2(accA[1]), lo2(accB[1]), hi2(accB[1])};
            float gz[4] = {lo2(accA[2]), hi2(accA[2]), lo2(accB[2]), hi2(accB[2])};
            float go[4] = {lo2(accA[3]), hi2(accA[3]), lo2(accB[3]), hi2(accB[3])};
            float h0new[4];
            #pragma unroll
            for (int nb = 0; nb < NBT; nb++) {
                float ig = sigmoidf_(gi[nb]);
                float fg = sigmoidf_(gf[nb]);
                float zg = tanhf_(gz[nb]);
                float og = sigmoidf_(go[nb]);
                c0[nb] = fg * c0[nb] + ig * zg;
                h0new[nb] = og * tanhf_(c0[nb]);
            }
            *(float4*)(h0s + q * HBS + u * NBC + bb) =
                make_float4(h0new[0], h0new[1], h0new[2], h0new[3]);
        }
        __syncthreads();   // h0(t) visible to layer 1

        // ===== layer 1 : gates = b1 + Wih1 @ h0(t) + Whh1 @ h1(t-1) =====
        #pragma unroll
        for (int g = 0; g < 4; g++) { accA[g] = rb1[g]; accB[g] = rb1[g]; }
        {
            const float* hap = h0s + q * HBS + bb;   // h0(t)
            const float* hbp = h1s + p * HBS + bb;   // h1(t-1)
            for (int j4 = 0; j4 < JP; j4 += 4) {
                float4 ai = *(const float4*)(w1ir[0] + j4);
                float4 af = *(const float4*)(w1ir[1] + j4);
                float4 ag = *(const float4*)(w1ir[2] + j4);
                float4 ao = *(const float4*)(w1ir[3] + j4);
                float4 ri = *(const float4*)(w1hr[0] + j4);
                float4 rf = *(const float4*)(w1hr[1] + j4);
                float4 rg = *(const float4*)(w1hr[2] + j4);
                float4 ro = *(const float4*)(w1hr[3] + j4);
                ulonglong2 a0 = *(const ulonglong2*)(hap + (j4 + 0) * NBC);
                ulonglong2 a1 = *(const ulonglong2*)(hap + (j4 + 1) * NBC);
                ulonglong2 a2 = *(const ulonglong2*)(hap + (j4 + 2) * NBC);
                ulonglong2 a3 = *(const ulonglong2*)(hap + (j4 + 3) * NBC);
                ulonglong2 b0 = *(const ulonglong2*)(hbp + (j4 + 0) * NBC);
                ulonglong2 b1 = *(const ulonglong2*)(hbp + (j4 + 1) * NBC);
                ulonglong2 b2 = *(const ulonglong2*)(hbp + (j4 + 2) * NBC);
                ulonglong2 b3 = *(const ulonglong2*)(hbp + (j4 + 3) * NBC);

                fma2(accA[0], pk2(ai.x, ai.x), a0.x); fma2(accB[0], pk2(ai.x, ai.x), a0.y);
                fma2(accA[1], pk2(af.x, af.x), a0.x); fma2(accB[1], pk2(af.x, af.x), a0.y);
                fma2(accA[2], pk2(ag.x, ag.x), a0.x); fma2(accB[2], pk2(ag.x, ag.x), a0.y);
                fma2(accA[3], pk2(ao.x, ao.x), a0.x); fma2(accB[3], pk2(ao.x, ao.x), a0.y);
                fma2(accA[0], pk2(ri.x, ri.x), b0.x); fma2(accB[0], pk2(ri.x, ri.x), b0.y);
                fma2(accA[1], pk2(rf.x, rf.x), b0.x); fma2(accB[1], pk2(rf.x, rf.x), b0.y);
                fma2(accA[2], pk2(rg.x, rg.x), b0.x); fma2(accB[2], pk2(rg.x, rg.x), b0.y);
                fma2(accA[3], pk2(ro.x, ro.x), b0.x); fma2(accB[3], pk2(ro.x, ro.x), b0.y);

                fma2(accA[0], pk2(ai.y, ai.y), a1.x); fma2(accB[0], pk2(ai.y, ai.y), a1.y);
                fma2(accA[1], pk2(af.y, af.y), a1.x); fma2(accB[1], pk2(af.y, af.y), a1.y);
                fma2(accA[2], pk2(ag.y, ag.y), a1.x); fma2(accB[2], pk2(ag.y, ag.y), a1.y);
                fma2(accA[3], pk2(ao.y, ao.y), a1.x); fma2(accB[3], pk2(ao.y, ao.y), a1.y);
                fma2(accA[0], pk2(ri.y, ri.y), b1.x); fma2(accB[0], pk2(ri.y, ri.y), b1.y);
                fma2(accA[1], pk2(rf.y, rf.y), b1.x); fma2(accB[1], pk2(rf.y, rf.y), b1.y);
                fma2(accA[2], pk2(rg.y, rg.y), b1.x); fma2(accB[2], pk2(rg.y, rg.y), b1.y);
                fma2(accA[3], pk2(ro.y, ro.y), b1.x); fma2(accB[3], pk2(ro.y, ro.y), b1.y);

                fma2(accA[0], pk2(ai.z, ai.z), a2.x); fma2(accB[0], pk2(ai.z, ai.z), a2.y);
                fma2(accA[1], pk2(af.z, af.z), a2.x); fma2(accB[1], pk2(af.z, af.z), a2.y);
                fma2(accA[2], pk2(ag.z, ag.z), a2.x); fma2(accB[2], pk2(ag.z, ag.z), a2.y);
                fma2(accA[3], pk2(ao.z, ao.z), a2.x); fma2(accB[3], pk2(ao.z, ao.z), a2.y);
                fma2(accA[0], pk2(ri.z, ri.z), b2.x); fma2(accB[0], pk2(ri.z, ri.z), b2.y);
                fma2(accA[1], pk2(rf.z, rf.z), b2.x); fma2(accB[1], pk2(rf.z, rf.z), b2.y);
                fma2(accA[2], pk2(rg.z, rg.z), b2.x); fma2(accB[2], pk2(rg.z, rg.z), b2.y);
                fma2(accA[3], pk2(ro.z, ro.z), b2.x); fma2(accB[3], pk2(ro.z, ro.z), b2.y);

                fma2(accA[0], pk2(ai.w, ai.w), a3.x); fma2(accB[0], pk2(ai.w, ai.w), a3.y);
                fma2(accA[1], pk2(af.w, af.w), a3.x); fma2(accB[1], pk2(af.w, af.w), a3.y);
                fma2(accA[2], pk2(ag.w, ag.w), a3.x); fma2(accB[2], pk2(ag.w, ag.w), a3.y);
                fma2(accA[3], pk2(ao.w, ao.w), a3.x); fma2(accB[3], pk2(ao.w, ao.w), a3.y);
                fma2(accA[0], pk2(ri.w, ri.w), b3.x); fma2(accB[0], pk2(ri.w, ri.w), b3.y);
                fma2(accA[1], pk2(rf.w, rf.w), b3.x); fma2(accB[1], pk2(rf.w, rf.w), b3.y);
                fma2(accA[2], pk2(rg.w, rg.w), b3.x); fma2(accB[2], pk2(rg.w, rg.w), b3.y);
                fma2(accA[3], pk2(ro.w, ro.w), b3.x); fma2(accB[3], pk2(ro.w, ro.w), b3.y);
            }
        }
        {
            float gi[4] = {lo2(accA[0]), hi2(accA[0]), lo2(accB[0]), hi2(accB[0])};
            float gf[4] = {lo2(accA[1]), hi2(accA[1]), lo2(accB[1]), hi2(accB[1])};
            float gz[4] = {lo2(accA[2]), hi2(accA[2]), lo2(accB[2]), hi2(accB[2])};
            float go[4] = {lo2(accA[3]), hi2(accA[3]), lo2(accB[3]), hi2(accB[3])};
            float h1new[4];
            #pragma unroll
            for (int nb = 0; nb < NBT; nb++) {
                float ig = sigmoidf_(gi[nb]);
                float fg = sigmoidf_(gf[nb]);
                float zg = tanhf_(gz[nb]);
                float og = sigmoidf_(go[nb]);
                c1[nb] = fg * c1[nb] + ig * zg;
                h1new[nb] = og * tanhf_(c1[nb]);
            }
            *(float4*)(h1s + q * HBS + u * NBC + bb) =
                make_float4(h1new[0], h1new[1], h1new[2], h1new[3]);
        }
        __syncthreads();   // h1(t) + h0 buffer reuse safe for next step

        #pragma unroll
        for (int nb = 0; nb < NBT; nb++) xv[nb] = xvn[nb];
        p = q;
    }

    // ===== final projection: out[b] = h1_last[:, b] . fcw + fcb =====
    // T=512 even -> final h1 in buffer 0
    if (tid < NBC) {
        float acc = fcws[HID];
        const float* hf = h1s;   // buffer 0
        #pragma unroll 10
        for (int uu = 0; uu < HID; uu++)
            acc += hf[uu * NBC + tid] * fcws[uu];
        out[blockIdx.x * NBC + tid] = acc;
    }
}

extern "C" void kernel_launch(void* const* d_in, const int* in_sizes, int n_in,
                              void* d_out, int out_size)
{
    const float* x    = (const float*)d_in[0];
    const float* Wih0 = (const float*)d_in[1];
    const float* Whh0 = (const float*)d_in[2];
    const float* bih0 = (const float*)d_in[3];
    const float* bhh0 = (const float*)d_in[4];
    const float* Wih1 = (const float*)d_in[5];
    const float* Whh1 = (const float*)d_in[6];
    const float* bih1 = (const float*)d_in[7];
    const float* bhh1 = (const float*)d_in[8];
    const float* fcw  = (const float*)d_in[9];
    const float* fcb  = (const float*)d_in[10];
    float* out = (float*)d_out;

    cudaFuncSetAttribute(lstm_fused_kernel,
                         cudaFuncAttributeMaxDynamicSharedMemorySize, SMEM_BYTES);
    lstm_fused_kernel<<<NCTAS, NTHREADS, SMEM_BYTES>>>(
        x, Wih0, Whh0, bih0, bhh0, Wih1, Whh1, bih1, bhh1, fcw, fcb, out);
}